// round 16
// baseline (speedup 1.0000x reference)
#include <cuda_runtime.h>
#include <cuda_fp16.h>
#include <cstdint>

// ============================================================================
// MIPT cell, sm_103-portable path (compute_103 virtual arch: no tcgen05).
// fp16 mma.sync m16n8k16 GEMM, CTA 128x64 (16 cols x 4 segments), 8 warps
// (4m x 2n, warp tile 32x32), swizzled 128B smem rows (no padding),
// 3 CTAs/SM (6 warps/SMSP) for latency hiding:
//   proj = e_t @ [W_p; W_th; W_r; W_i]^T + b   (B=8192, D=2048)
// fused with sigmoid / sincos rotation / blend epilogue.
// ============================================================================

#define D_DIM 2048
#define B_DIM 8192
#define BM 128
#define BN 64               // 16 cols x 4 segments
#define BK 64               // K halfs per stage (128B rows)
#define NITER (D_DIM / BK)  // 32
#define STAGES 3
#define ROWB 128            // swizzled rows, no pad
#define STAGE_A_BYTES (BM * ROWB)                // 16384
#define STAGE_B_BYTES (BN * ROWB)                // 8192
#define STAGE_BYTES (STAGE_A_BYTES + STAGE_B_BYTES)  // 24576
#define SMEM_MAIN (STAGES * STAGE_BYTES)         // 73728 (x3 CTA = 221KB)
#define EPI_STRIDE 68
#define NTHREADS 256

// ---------------------------------------------------------------------------
// Scratch: fp16-rounded operands (__device__ globals; alloc-free rule)
// ---------------------------------------------------------------------------
__device__ __half g_Ah[(size_t)B_DIM * D_DIM];        // 32 MB
__device__ __half g_Wh[(size_t)4 * D_DIM * D_DIM];    // 32 MB

__device__ __forceinline__ uint32_t smem_u32(const void* p) {
    uint32_t a;
    asm("{ .reg .u64 t; cvta.to.shared.u64 t, %1; cvt.u32.u64 %0, t; }" : "=r"(a) : "l"(p));
    return a;
}
__device__ __forceinline__ void cp_async16(uint32_t dst, const void* src) {
    asm volatile("cp.async.cg.shared.global [%0], [%1], 16;" :: "r"(dst), "l"(src));
}
__device__ __forceinline__ void prefetch_l2(const void* p) {
    asm volatile("prefetch.global.L2 [%0];" :: "l"(p));
}
__device__ __forceinline__ void mma_f16(float* d, const uint32_t* a, const uint32_t* b) {
    asm volatile(
        "mma.sync.aligned.m16n8k16.row.col.f32.f16.f16.f32 "
        "{%0,%1,%2,%3}, {%4,%5,%6,%7}, {%8,%9}, {%0,%1,%2,%3};"
        : "+f"(d[0]), "+f"(d[1]), "+f"(d[2]), "+f"(d[3])
        : "r"(a[0]), "r"(a[1]), "r"(a[2]), "r"(a[3]), "r"(b[0]), "r"(b[1]));
}
__device__ __forceinline__ void ldsm_x4(uint32_t* r, uint32_t addr) {
    asm volatile("ldmatrix.sync.aligned.m8n8.x4.shared.b16 {%0,%1,%2,%3}, [%4];"
                 : "=r"(r[0]), "=r"(r[1]), "=r"(r[2]), "=r"(r[3]) : "r"(addr));
}

// ---------------------------------------------------------------------------
// Merged prepass: one launch converts e_t + all 4 W matrices to fp16 (RN).
// ---------------------------------------------------------------------------
__global__ void f2h_all_kernel(const float4* __restrict__ eA,
                               const float4* __restrict__ w0,
                               const float4* __restrict__ w1,
                               const float4* __restrict__ w2,
                               const float4* __restrict__ w3,
                               __half2* __restrict__ dA,
                               __half2* __restrict__ dW,
                               int n4w) {            // float4 count per W
    const int y = blockIdx.y;
    const float4* src;
    __half2* dst;
    int n4;
    if (y == 0) { src = eA; dst = dA; n4 = n4w * 4; }           // e_t = 4 W's
    else {
        src = (y == 1) ? w0 : (y == 2) ? w1 : (y == 3) ? w2 : w3;
        dst = dW + (size_t)(y - 1) * n4w * 2;
        n4 = n4w;
    }
    const int stride = gridDim.x * blockDim.x;
    for (int i = blockIdx.x * blockDim.x + threadIdx.x; i < n4; i += stride) {
        float4 v = src[i];
        dst[2 * i]     = __floats2half2_rn(v.x, v.y);
        dst[2 * i + 1] = __floats2half2_rn(v.z, v.w);
    }
}

// ---------------------------------------------------------------------------
// Fused GEMM + epilogue
// ---------------------------------------------------------------------------
__global__ void __launch_bounds__(NTHREADS, 3)
mipt_kernel(const __half* __restrict__ gA, const __half* __restrict__ gW,
            const float* __restrict__ h_prev,
            const float* __restrict__ b_p, const float* __restrict__ b_th,
            const float* __restrict__ b_r, const float* __restrict__ b_i,
            float* __restrict__ out) {
    extern __shared__ float sm[];
    const int tid = threadIdx.x;
    const int bx = blockIdx.x;
    const int mt = bx & 63;          // m-tile (64)
    const int nt = bx >> 6;          // n-tile (128; 16 cols per segment)
    const uint32_t sbase = smem_u32(sm);

    const int wid = tid >> 5, lane = tid & 31;
    const int g = lane >> 2, tg = lane & 3;
    const int wm = (wid & 3) * 32;   // warp m offset (4 m-warps)
    const int wn = (wid >> 2) * 32;  // warp n offset (2 n-warps)

    // swizzle: chunk q of row r lives at r*128 + ((q ^ (r&7))<<4).
    const uint32_t s = lane & 7;                 // == row&7 for both operands
    const uint32_t baseA = (uint32_t)(wm + (lane & 15)) * ROWB;
    const uint32_t hiA = lane >> 4;              // chunk bit from k-half
    const uint32_t baseB =
        (uint32_t)(wn + (lane & 7) + ((lane >> 4) << 3)) * ROWB;
    const uint32_t hiB = (lane >> 3) & 1;

    // ---- async stage loader: A [128 x 64h] + B [64 x 64h] = 1536 chunks ----
    auto load_stage = [&](int st, int k0) {
        const uint32_t smA = sbase + st * STAGE_BYTES;
        #pragma unroll
        for (int r = 0; r < 6; r++) {
            const int ch = tid + r * NTHREADS;    // 0..1535
            const int row = ch >> 3, q = ch & 7;  // 8 x 16B chunks per row
            const uint32_t sw = (uint32_t)(q ^ (row & 7)) << 4;
            if (row < BM) {
                const __half* ga = gA + (size_t)(mt * 128 + row) * D_DIM + k0 + q * 8;
                cp_async16(smA + row * ROWB + sw, ga);
            } else {
                const int br = row - BM;          // 0..63
                const int j = br >> 4, c = br & 15;
                const __half* gb = gW + (size_t)j * (D_DIM * D_DIM)
                                      + (size_t)(nt * 16 + c) * D_DIM + k0 + q * 8;
                cp_async16(smA + STAGE_A_BYTES + br * ROWB
                           + (uint32_t)(q ^ (br & 7)) * 16u, gb);
            }
        }
        asm volatile("cp.async.commit_group;");
    };

    float acc[2][4][4] = {};          // [mi][ni][regs] : 32x32 warp tile
    uint32_t af[2][4];                // single-buffered (6 warps/SMSP hide lat)
    uint32_t bf[2][4];                // [nb][regs], nb -> ni=2nb,2nb+1

    load_stage(0, 0);
    load_stage(1, BK);

    // ---- L2-prefetch this CTA's epilogue inputs (h_prev slice + biases) ----
    {
        const int prow = tid >> 1;            // 0..127
        const int half = tid & 1;             // 0: re, 1: im
        prefetch_l2(h_prev + (size_t)(mt * 128 + prow) * (2 * D_DIM)
                    + (size_t)half * D_DIM + nt * 16);
        if (tid < 4) {
            const float* bsel = (tid == 0) ? b_p : (tid == 1) ? b_th
                              : (tid == 2) ? b_r : b_i;
            prefetch_l2(bsel + nt * 16);
        }
    }

    for (int it = 0; it < NITER; it++) {
        asm volatile("cp.async.wait_group %0;" :: "n"(STAGES - 2));
        __syncthreads();
        const int cs = it % STAGES;
        const uint32_t sA = sbase + (uint32_t)cs * STAGE_BYTES;
        const uint32_t sB = sA + STAGE_A_BYTES;

        if (it + STAGES - 1 < NITER)
            load_stage((it + STAGES - 1) % STAGES, (it + STAGES - 1) * BK);

        #pragma unroll
        for (int kk = 0; kk < 4; kk++) {          // 4 x k16 per stage
            const uint32_t qa = ((uint32_t)(kk * 2) + hiA) ^ s;
            const uint32_t qb = ((uint32_t)(kk * 2) + hiB) ^ s;
            #pragma unroll
            for (int mi = 0; mi < 2; mi++)
                ldsm_x4(af[mi], sA + baseA + (uint32_t)mi * (16u * ROWB)
                                + (qa << 4));
            #pragma unroll
            for (int nb = 0; nb < 2; nb++)
                ldsm_x4(bf[nb], sB + baseB + (uint32_t)nb * (16u * ROWB)
                                + (qb << 4));
            #pragma unroll
            for (int mi = 0; mi < 2; mi++)
                #pragma unroll
                for (int nb = 0; nb < 2; nb++) {
                    mma_f16(acc[mi][2 * nb],     af[mi], &bf[nb][0]);
                    mma_f16(acc[mi][2 * nb + 1], af[mi], &bf[nb][2]);
                }
        }
    }

    // ---- stage accumulators through smem: thread gathers (p,th,re,im) ----
    asm volatile("cp.async.wait_group 0;");
    __syncthreads();
    float* epi = sm;   // 128 x EPI_STRIDE = 34.8 KB <= SMEM_MAIN
    #pragma unroll
    for (int mi = 0; mi < 2; mi++)
        #pragma unroll
        for (int ni = 0; ni < 4; ni++) {
            const int r = wm + mi * 16 + g;
            const int n = wn + ni * 8 + 2 * tg;
            epi[r * EPI_STRIDE + n]           = acc[mi][ni][0];
            epi[r * EPI_STRIDE + n + 1]       = acc[mi][ni][1];
            epi[(r + 8) * EPI_STRIDE + n]     = acc[mi][ni][2];
            epi[(r + 8) * EPI_STRIDE + n + 1] = acc[mi][ni][3];
        }
    __syncthreads();

    // ---- fused epilogue: sigmoid gate + rotation + blend ----
    const int rowt = tid >> 2;            // 0..63
    const int cb = (tid & 3) * 4;         // 0..12
    const int ng = nt * 16 + cb;
    const float4 bp = *(const float4*)&b_p[ng];
    const float4 bt = *(const float4*)&b_th[ng];
    const float4 br = *(const float4*)&b_r[ng];
    const float4 bi = *(const float4*)&b_i[ng];

    #pragma unroll
    for (int rep = 0; rep < 2; rep++) {
        const int m = rep * 64 + rowt;
        const size_t gm = (size_t)(mt * 128 + m);
        const float4 pl = *(const float4*)&epi[m * EPI_STRIDE + 0 * 16 + cb];
        const float4 th = *(const float4*)&epi[m * EPI_STRIDE + 1 * 16 + cb];
        const float4 xr = *(const float4*)&epi[m * EPI_STRIDE + 2 * 16 + cb];
        const float4 xi = *(const float4*)&epi[m * EPI_STRIDE + 3 * 16 + cb];
        const float4 hr = *(const float4*)&h_prev[gm * (2 * D_DIM) + ng];
        const float4 hi = *(const float4*)&h_prev[gm * (2 * D_DIM) + D_DIM + ng];

        float plv[4] = {pl.x + bp.x, pl.y + bp.y, pl.z + bp.z, pl.w + bp.w};
        float thv[4] = {th.x + bt.x, th.y + bt.y, th.z + bt.z, th.w + bt.w};
        float xrv[4] = {xr.x + br.x, xr.y + br.y, xr.z + br.z, xr.w + br.w};
        float xiv[4] = {xi.x + bi.x, xi.y + bi.y, xi.z + bi.z, xi.w + bi.w};
        float hrv[4] = {hr.x, hr.y, hr.z, hr.w};
        float hiv[4] = {hi.x, hi.y, hi.z, hi.w};
        float ore[4], oim[4];
        #pragma unroll
        for (int c = 0; c < 4; c++) {
            const float p = 1.0f / (1.0f + __expf(-plv[c]));
            float sn, cs;
            __sincosf(thv[c], &sn, &cs);
            const float rre = cs * hrv[c] - sn * hiv[c];
            const float rim = sn * hrv[c] + cs * hiv[c];
            ore[c] = rre + p * (xrv[c] - rre);
            oim[c] = rim + p * (xiv[c] - rim);
        }
        *(float4*)&out[gm * (2 * D_DIM) + ng] =
            make_float4(ore[0], ore[1], ore[2], ore[3]);
        *(float4*)&out[gm * (2 * D_DIM) + D_DIM + ng] =
            make_float4(oim[0], oim[1], oim[2], oim[3]);
    }
}

// ---------------------------------------------------------------------------
// Host
// ---------------------------------------------------------------------------
extern "C" void kernel_launch(void* const* d_in, const int* in_sizes, int n_in,
                              void* d_out, int out_size) {
    const float* e_t    = (const float*)d_in[0];
    const float* h_prev = (const float*)d_in[1];
    const float* W_p    = (const float*)d_in[2];
    const float* b_p    = (const float*)d_in[3];
    const float* W_th   = (const float*)d_in[4];
    const float* b_th   = (const float*)d_in[5];
    const float* W_r    = (const float*)d_in[6];
    const float* b_r    = (const float*)d_in[7];
    const float* W_i    = (const float*)d_in[8];
    const float* b_i    = (const float*)d_in[9];
    float* out = (float*)d_out;

    __half* sA = nullptr; __half* sW = nullptr;
    cudaGetSymbolAddress((void**)&sA, g_Ah);
    cudaGetSymbolAddress((void**)&sW, g_Wh);

    const size_t nW = (size_t)D_DIM * D_DIM;
    f2h_all_kernel<<<dim3(640, 5), 256>>>(
        (const float4*)e_t, (const float4*)W_p, (const float4*)W_th,
        (const float4*)W_r, (const float4*)W_i,
        (__half2*)sA, (__half2*)sW, (int)(nW / 4));

    cudaFuncSetAttribute(mipt_kernel, cudaFuncAttributeMaxDynamicSharedMemorySize,
                         SMEM_MAIN);
    // grid: nt-major so a wave shares W tiles; A stays L2-resident
    mipt_kernel<<<64 * 128, NTHREADS, SMEM_MAIN>>>(sA, sW, h_prev,
                                                   b_p, b_th, b_r, b_i, out);
}